// round 15
// baseline (speedup 1.0000x reference)
#include <cuda_runtime.h>

// ---------------- scratch (sizes fixed: N=50000, E=400000) ----------------
__device__ float g_agg [50048  * 80];   // per-node gated sums: 32 silu'd scalars + 48 vec comps
__device__ float g_mid [400000 * 40];   // stage-1 per-edge intermediate (e-major)

#define I2f   0.70710678118654752f
#define I3f   0.57735026918962576f
#define R128f 0.08838834764831845f
#define R32f  0.17677669529663687f

__device__ __forceinline__ float sigm_f(float x) {
    return __fdividef(1.f, 1.f + __expf(-x));
}

__device__ __forceinline__ void wload(float* __restrict__ dst, const float* __restrict__ src,
                                      int nf4, float sc, int tid, int nt) {
    for (int t = tid; t < nf4; t += nt) {
        float4 v = reinterpret_cast<const float4*>(src)[t];
        v.x *= sc; v.y *= sc; v.z *= sc; v.w *= sc;
        reinterpret_cast<float4*>(dst)[t] = v;
    }
}
__device__ __forceinline__ void wslice(float* __restrict__ dst, const float* __restrict__ src,
                                       int rows, int srcF4, int dstF4, int off4,
                                       float sc, int tid, int nt) {
    int n = rows * dstF4;
    for (int t = tid; t < n; t += nt) {
        int r = t / dstF4, o = t - r * dstF4;
        float4 v = reinterpret_cast<const float4*>(src)[r * srcF4 + off4 + o];
        v.x *= sc; v.y *= sc; v.z *= sc; v.w *= sc;
        reinterpret_cast<float4*>(dst)[t] = v;
    }
}
template<int K4>
__device__ __forceinline__ void fma_k(float* acc, const float* __restrict__ w, float p) {
#pragma unroll
    for (int k = 0; k < K4; k++) {
        float4 ww = reinterpret_cast<const float4*>(w)[k];
        acc[4 * k + 0] += p * ww.x; acc[4 * k + 1] += p * ww.y;
        acc[4 * k + 2] += p * ww.z; acc[4 * k + 3] += p * ww.w;
    }
}
__device__ __forceinline__ void fma_vo8(float* vo, const float* A, float bx, float by, float bz) {
#pragma unroll
    for (int k = 0; k < 8; k++) {
        vo[3 * k + 0] += A[k] * bx; vo[3 * k + 1] += A[k] * by; vo[3 * k + 2] += A[k] * bz;
    }
}
__device__ __forceinline__ void fma_cross8(float* vo, const float* __restrict__ w,
                                           float cx, float cy, float cz) {
#pragma unroll
    for (int q = 0; q < 2; q++) {
        float4 ww = reinterpret_cast<const float4*>(w)[q];
        vo[12 * q + 0]  += cx * ww.x; vo[12 * q + 1]  += cy * ww.x; vo[12 * q + 2]  += cz * ww.x;
        vo[12 * q + 3]  += cx * ww.y; vo[12 * q + 4]  += cy * ww.y; vo[12 * q + 5]  += cz * ww.y;
        vo[12 * q + 6]  += cx * ww.z; vo[12 * q + 7]  += cy * ww.z; vo[12 * q + 8]  += cz * ww.z;
        vo[12 * q + 9]  += cx * ww.w; vo[12 * q + 10] += cy * ww.w; vo[12 * q + 11] += cz * ww.w;
    }
}
__device__ __forceinline__ void ld_f(float* dst, const float* __restrict__ src, int nf4) {
#pragma unroll
    for (int q = 0; q < 6; q++)
        if (q < nf4) reinterpret_cast<float4*>(dst)[q] =
            __ldg(reinterpret_cast<const float4*>(src) + q);
}

// ---------------- kernels ----------------
__global__ void zero_kernel(int n) {
    int i = blockIdx.x * 256 + threadIdx.x;
    if (i < n) g_agg[i] = 0.f;
}

// stage1 fused: all 5 paths per edge, inputs gathered once -> g_mid[e][0:40)
__global__ __launch_bounds__(128, 4) void stage1_kernel(
    const float* __restrict__ ns, const float* __restrict__ nv,
    const int* __restrict__ eidx,
    const float* __restrict__ W1ss, const float* __restrict__ W1sv,
    const float* __restrict__ W1vs, const float* __restrict__ W1vvs,
    const float* __restrict__ W1vvv, int E)
{
    __shared__ float wss[4096], wvvs[1024], wsv[1024], wvs[1024], wvvv[512];
    int tid = threadIdx.x;
    wload(wss,  W1ss,  1024, I2f / 16.f,     tid, 128);
    wload(wvvs, W1vvs,  256, I2f * I3f / 8.f, tid, 128);
    wload(wsv,  W1sv,   256, I3f * R128f,    tid, 128);
    wload(wvs,  W1vs,   256, I3f * R128f,    tid, 128);
    wload(wvvv, W1vvv,  128, I2f * I3f / 8.f, tid, 128);
    __syncthreads();
    int e = blockIdx.x * 128 + tid;
    if (e >= E) return;
    int r = eidx[e], c = eidx[E + e];

    float s1[16], s2[16], v1[24], v2[24];
    ld_f(s1, ns + (size_t)r * 16, 4);
    ld_f(s2, ns + (size_t)c * 16, 4);
    ld_f(v1, nv + (size_t)r * 24, 6);
    ld_f(v2, nv + (size_t)c * 24, 6);

    // ---- scalar paths ----
    {
        float acc[16];
#pragma unroll
        for (int k = 0; k < 16; k++) acc[k] = 0.f;
#pragma unroll 1
        for (int i = 0; i < 16; i++) {
            float a = s1[i];
#pragma unroll 2
            for (int j = 0; j < 16; j++)
                fma_k<4>(acc, &wss[(i * 16 + j) * 16], a * s2[j]);
        }
#pragma unroll 1
        for (int i = 0; i < 8; i++) {
            float ax = v1[3 * i], ay = v1[3 * i + 1], az = v1[3 * i + 2];
#pragma unroll 2
            for (int j = 0; j < 8; j++) {
                float d = ax * v2[3 * j] + ay * v2[3 * j + 1] + az * v2[3 * j + 2];
                fma_k<4>(acc, &wvvs[(i * 8 + j) * 16], d);
            }
        }
        float* o = &g_mid[(size_t)e * 40];
#pragma unroll
        for (int q = 0; q < 4; q++)
            reinterpret_cast<float4*>(o)[q] = reinterpret_cast<float4*>(acc)[q];
    }
    // ---- vector paths ----
    {
        float vo[24];
#pragma unroll
        for (int k = 0; k < 24; k++) vo[k] = 0.f;
#pragma unroll 1
        for (int j = 0; j < 8; j++) {
            float A[8];
#pragma unroll
            for (int k = 0; k < 8; k++) A[k] = 0.f;
#pragma unroll 2
            for (int i = 0; i < 16; i++)
                fma_k<2>(A, &wsv[(i * 8 + j) * 8], s1[i]);
            fma_vo8(vo, A, v2[3 * j], v2[3 * j + 1], v2[3 * j + 2]);
        }
#pragma unroll 1
        for (int i = 0; i < 8; i++) {
            float A[8];
#pragma unroll
            for (int k = 0; k < 8; k++) A[k] = 0.f;
#pragma unroll 2
            for (int j = 0; j < 16; j++)
                fma_k<2>(A, &wvs[(i * 16 + j) * 8], s2[j]);
            fma_vo8(vo, A, v1[3 * i], v1[3 * i + 1], v1[3 * i + 2]);
        }
#pragma unroll 1
        for (int i = 0; i < 8; i++) {
            float ax = v1[3 * i], ay = v1[3 * i + 1], az = v1[3 * i + 2];
#pragma unroll 1
            for (int j = 0; j < 8; j++) {
                float bx = v2[3 * j], by = v2[3 * j + 1], bz = v2[3 * j + 2];
                fma_cross8(vo, &wvvv[(i * 8 + j) * 8],
                           ay * bz - az * by, az * bx - ax * bz, ax * by - ay * bx);
            }
        }
        float* o = &g_mid[(size_t)e * 40 + 16];
#pragma unroll
        for (int q = 0; q < 6; q++)
            reinterpret_cast<float4*>(o)[q] = reinterpret_cast<float4*>(vo)[q];
    }
}

// stage2 fused: 3 scalar k-chunks (silu->atomic; gates->regs) then 2 vector k-chunks
// using register gates.
__global__ __launch_bounds__(128, 4) void stage2_kernel(
    const float* __restrict__ edge_s, const float* __restrict__ edge_v,
    const int* __restrict__ eidx,
    const float* __restrict__ W2ss, const float* __restrict__ W2vvs,
    const float* __restrict__ W2sv, const float* __restrict__ W2vs,
    const float* __restrict__ W2vvv, int E)
{
    __shared__ float ws[2048], wd[1024];          // scalar chunk slices
    __shared__ float wsv[1024], wvs[512], wvvv[512]; // vector chunk slices
    int tid = threadIdx.x;
    int e = blockIdx.x * 128 + tid;
    bool act = e < E;
    int c = 0;
    float ms[16], mv[24], es[8], ev[24];
    if (act) {
        c = eidx[E + e];
        const float* m = &g_mid[(size_t)e * 40];
#pragma unroll
        for (int q = 0; q < 4; q++) reinterpret_cast<float4*>(ms)[q] = reinterpret_cast<const float4*>(m)[q];
#pragma unroll
        for (int q = 0; q < 6; q++) reinterpret_cast<float4*>(mv)[q] = reinterpret_cast<const float4*>(m)[4 + q];
        ld_f(es, edge_s + (size_t)e * 8, 2);
        ld_f(ev, edge_v + (size_t)e * 24, 6);
    }
    float gate[16];

    // ---- scalar chunks ----
#pragma unroll 1
    for (int ch = 0; ch < 3; ch++) {
        __syncthreads();
        wslice(ws, W2ss, 128, 12, 4, ch * 4, I2f * R128f, tid, 128);
        wslice(wd, W2vvs, 64, 12, 4, ch * 4, I2f * I3f / 8.f, tid, 128);
        __syncthreads();
        if (!act) continue;
        float acc[16];
#pragma unroll
        for (int k = 0; k < 16; k++) acc[k] = 0.f;
#pragma unroll 1
        for (int i = 0; i < 16; i++) {
            float a = ms[i];
#pragma unroll 2
            for (int j = 0; j < 8; j++)
                fma_k<4>(acc, &ws[(i * 8 + j) * 16], a * es[j]);
        }
#pragma unroll 1
        for (int i = 0; i < 8; i++) {
            float ax = mv[3 * i], ay = mv[3 * i + 1], az = mv[3 * i + 2];
#pragma unroll 2
            for (int j = 0; j < 8; j++) {
                float d = ax * ev[3 * j] + ay * ev[3 * j + 1] + az * ev[3 * j + 2];
                fma_k<4>(acc, &wd[(i * 8 + j) * 16], d);
            }
        }
        if (ch < 2) {
            float* dst = &g_agg[(size_t)c * 80 + ch * 16];
#pragma unroll
            for (int t = 0; t < 16; t++)
                atomicAdd(dst + t, acc[t] * sigm_f(acc[t]));   // silu
        } else {
#pragma unroll
            for (int t = 0; t < 16; t++)
                gate[t] = sigm_f(acc[t]);
        }
    }

    // ---- vector chunks (gates in registers) ----
#pragma unroll 1
    for (int ch = 0; ch < 2; ch++) {
        __syncthreads();
        wslice(wsv, W2sv, 128, 4, 2, ch * 2, I3f * R128f, tid, 128);
        wslice(wvs, W2vs, 64, 4, 2, ch * 2, I3f / 8.f, tid, 128);
        wslice(wvvv, W2vvv, 64, 4, 2, ch * 2, I2f * I3f / 8.f, tid, 128);
        __syncthreads();
        if (!act) continue;
        float vo[24];
#pragma unroll
        for (int k = 0; k < 24; k++) vo[k] = 0.f;
#pragma unroll 1
        for (int j = 0; j < 8; j++) {
            float A[8];
#pragma unroll
            for (int k = 0; k < 8; k++) A[k] = 0.f;
#pragma unroll 2
            for (int i = 0; i < 16; i++)
                fma_k<2>(A, &wsv[(i * 8 + j) * 8], ms[i]);
            fma_vo8(vo, A, ev[3 * j], ev[3 * j + 1], ev[3 * j + 2]);
        }
#pragma unroll 1
        for (int i = 0; i < 8; i++) {
            float A[8];
#pragma unroll
            for (int k = 0; k < 8; k++) A[k] = 0.f;
#pragma unroll 2
            for (int j = 0; j < 8; j++)
                fma_k<2>(A, &wvs[(i * 8 + j) * 8], es[j]);
            fma_vo8(vo, A, mv[3 * i], mv[3 * i + 1], mv[3 * i + 2]);
        }
#pragma unroll 1
        for (int i = 0; i < 8; i++) {
            float ax = mv[3 * i], ay = mv[3 * i + 1], az = mv[3 * i + 2];
#pragma unroll 1
            for (int j = 0; j < 8; j++) {
                float bx = ev[3 * j], by = ev[3 * j + 1], bz = ev[3 * j + 2];
                fma_cross8(vo, &wvvv[(i * 8 + j) * 8],
                           ay * bz - az * by, az * bx - ax * bz, ax * by - ay * bx);
            }
        }
#pragma unroll
        for (int t = 0; t < 8; t++) {
            float g = gate[ch * 8 + t];
            float* dst = &g_agg[(size_t)c * 80 + 32 + (ch * 8 + t) * 3];
            atomicAdd(dst + 0, vo[3 * t + 0] * g);
            atomicAdd(dst + 1, vo[3 * t + 1] * g);
            atomicAdd(dst + 2, vo[3 * t + 2] * g);
        }
    }
}

// update fused (folds Lms/Lmv + Lus/Luv): 64-thread blocks for more independent
// blocks/SM (grid-limited kernel). Reads g_agg[n,80] directly, writes out.
__global__ __launch_bounds__(64, 8) void update_kernel(
    const float* __restrict__ ns, const float* __restrict__ nv,
    const float* __restrict__ W3ss, const float* __restrict__ W3vvs,
    const float* __restrict__ W3sv, const float* __restrict__ W3vs,
    const float* __restrict__ W3vvv,
    const float* __restrict__ Lms, const float* __restrict__ Lmv,
    const float* __restrict__ Lus, const float* __restrict__ Luv,
    float* __restrict__ out, int N)
{
    __shared__ float ws[4096], wd[1024];              // scalar slices
    __shared__ float wsv[1024], wvs[1024], wvvv[512]; // vector slices
    __shared__ float lms[512], lmv[128], lus[512], luv[128];
    int tid = threadIdx.x;
    wload(lms, Lms, 128, R32f, tid, 64);
    wload(lmv, Lmv, 32, 0.25f, tid, 64);
    wload(lus, Lus, 128, R32f, tid, 64);
    wload(luv, Luv, 32, 0.25f, tid, 64);
    __syncthreads();
    int n = blockIdx.x * 64 + tid;
    bool act = n < N;

    float s1[16], v1[24], s2[16], v2[24];
    if (act) {
        ld_f(s1, ns + (size_t)n * 16, 4);
        ld_f(v1, nv + (size_t)n * 24, 6);
        // ---- fold Lms/Lmv from aggregated (post-gate) sums ----
        const float* a = &g_agg[(size_t)n * 80];
#pragma unroll
        for (int k = 0; k < 16; k++) s2[k] = 0.f;
#pragma unroll 1
        for (int i = 0; i < 32; i++)
            fma_k<4>(s2, &lms[i * 16], a[i]);
#pragma unroll
        for (int k = 0; k < 24; k++) v2[k] = 0.f;
#pragma unroll 1
        for (int i = 0; i < 16; i++) {
            float ax = a[32 + 3 * i], ay = a[32 + 3 * i + 1], az = a[32 + 3 * i + 2];
            const float* w = &lmv[i * 8];
#pragma unroll
            for (int k = 0; k < 8; k++) {
                float ww = w[k];
                v2[3 * k + 0] += ax * ww; v2[3 * k + 1] += ay * ww; v2[3 * k + 2] += az * ww;
            }
        }
    }
    float os[16], ov[24], gate[16];
#pragma unroll
    for (int k = 0; k < 16; k++) os[k] = 0.f;
#pragma unroll
    for (int k = 0; k < 24; k++) ov[k] = 0.f;

    // ---- scalar chunks ----
#pragma unroll 1
    for (int ch = 0; ch < 3; ch++) {
        __syncthreads();
        wslice(ws, W3ss, 256, 12, 4, ch * 4, I2f / 16.f, tid, 64);
        wslice(wd, W3vvs, 64, 12, 4, ch * 4, I2f * I3f / 8.f, tid, 64);
        __syncthreads();
        if (!act) continue;
        float acc[16];
#pragma unroll
        for (int k = 0; k < 16; k++) acc[k] = 0.f;
#pragma unroll 1
        for (int i = 0; i < 16; i++) {
            float a = s1[i];
#pragma unroll 2
            for (int j = 0; j < 16; j++)
                fma_k<4>(acc, &ws[(i * 16 + j) * 16], a * s2[j]);
        }
#pragma unroll 1
        for (int i = 0; i < 8; i++) {
            float ax = v1[3 * i], ay = v1[3 * i + 1], az = v1[3 * i + 2];
#pragma unroll 2
            for (int j = 0; j < 8; j++) {
                float d = ax * v2[3 * j] + ay * v2[3 * j + 1] + az * v2[3 * j + 2];
                fma_k<4>(acc, &wd[(i * 8 + j) * 16], d);
            }
        }
        if (ch < 2) {
#pragma unroll 1
            for (int t = 0; t < 16; t++) {
                float a = acc[t] * sigm_f(acc[t]);           // silu
                fma_k<4>(os, &lus[(ch * 16 + t) * 16], a);   // fold Lus
            }
        } else {
#pragma unroll
            for (int t = 0; t < 16; t++)
                gate[t] = sigm_f(acc[t]);
        }
    }

    // ---- vector chunks ----
#pragma unroll 1
    for (int ch = 0; ch < 2; ch++) {
        __syncthreads();
        wslice(wsv, W3sv, 128, 4, 2, ch * 2, I3f * R128f, tid, 64);
        wslice(wvs, W3vs, 128, 4, 2, ch * 2, I3f * R128f, tid, 64);
        wslice(wvvv, W3vvv, 64, 4, 2, ch * 2, I2f * I3f / 8.f, tid, 64);
        __syncthreads();
        if (!act) continue;
        float vo[24];
#pragma unroll
        for (int k = 0; k < 24; k++) vo[k] = 0.f;
#pragma unroll 1
        for (int j = 0; j < 8; j++) {
            float A[8];
#pragma unroll
            for (int k = 0; k < 8; k++) A[k] = 0.f;
#pragma unroll 2
            for (int i = 0; i < 16; i++)
                fma_k<2>(A, &wsv[(i * 8 + j) * 8], s1[i]);
            fma_vo8(vo, A, v2[3 * j], v2[3 * j + 1], v2[3 * j + 2]);
        }
#pragma unroll 1
        for (int i = 0; i < 8; i++) {
            float A[8];
#pragma unroll
            for (int k = 0; k < 8; k++) A[k] = 0.f;
#pragma unroll 2
            for (int j = 0; j < 16; j++)
                fma_k<2>(A, &wvs[(i * 16 + j) * 8], s2[j]);
            fma_vo8(vo, A, v1[3 * i], v1[3 * i + 1], v1[3 * i + 2]);
        }
#pragma unroll 1
        for (int i = 0; i < 8; i++) {
            float ax = v1[3 * i], ay = v1[3 * i + 1], az = v1[3 * i + 2];
#pragma unroll 1
            for (int j = 0; j < 8; j++) {
                float bx = v2[3 * j], by = v2[3 * j + 1], bz = v2[3 * j + 2];
                float cx = ay * bz - az * by, cy = az * bx - ax * bz, cz = ax * by - ay * bx;
                fma_cross8(vo, &wvvv[(i * 8 + j) * 8], cx, cy, cz);
            }
        }
        // gate + fold Luv
#pragma unroll 1
        for (int t = 0; t < 8; t++) {
            float g = gate[ch * 8 + t];
            float gx = vo[3 * t + 0] * g, gy = vo[3 * t + 1] * g, gz = vo[3 * t + 2] * g;
            const float* w = &luv[(ch * 8 + t) * 8];
#pragma unroll
            for (int k = 0; k < 8; k++) {
                float ww = w[k];
                ov[3 * k + 0] += gx * ww; ov[3 * k + 1] += gy * ww; ov[3 * k + 2] += gz * ww;
            }
        }
    }
    if (act) {
        float* o = out + (size_t)n * 40;
#pragma unroll
        for (int q = 0; q < 4; q++) reinterpret_cast<float4*>(o)[q] = reinterpret_cast<float4*>(os)[q];
#pragma unroll
        for (int q = 0; q < 6; q++) reinterpret_cast<float4*>(o)[4 + q] = reinterpret_cast<float4*>(ov)[q];
    }
}

// ---------------- launch ----------------
extern "C" void kernel_launch(void* const* d_in, const int* in_sizes, int n_in,
                              void* d_out, int out_size) {
    const float* node_s = (const float*)d_in[0];
    const float* node_v = (const float*)d_in[1];
    const float* edge_s = (const float*)d_in[3];
    const float* edge_v = (const float*)d_in[4];
    const int*   eidx   = (const int*)d_in[5];
    const float* W1ss = (const float*)d_in[6];
    const float* W1sv = (const float*)d_in[7];
    const float* W1vs = (const float*)d_in[8];
    const float* W1vvs = (const float*)d_in[9];
    const float* W1vvv = (const float*)d_in[10];
    const float* W2ss = (const float*)d_in[11];
    const float* W2sv = (const float*)d_in[12];
    const float* W2vs = (const float*)d_in[13];
    const float* W2vvs = (const float*)d_in[14];
    const float* W2vvv = (const float*)d_in[15];
    const float* Lms = (const float*)d_in[16];
    const float* Lmv = (const float*)d_in[17];
    const float* W3ss = (const float*)d_in[18];
    const float* W3sv = (const float*)d_in[19];
    const float* W3vs = (const float*)d_in[20];
    const float* W3vvs = (const float*)d_in[21];
    const float* W3vvv = (const float*)d_in[22];
    const float* Lus = (const float*)d_in[23];
    const float* Luv = (const float*)d_in[24];
    float* out = (float*)d_out;

    int N = in_sizes[0] / 16;
    int E = in_sizes[3] / 8;
    int gE = (E + 127) / 128;
    int gN = (N + 63) / 64;

    zero_kernel<<<(N * 80 + 255) / 256, 256>>>(N * 80);
    stage1_kernel<<<gE, 128>>>(node_s, node_v, eidx, W1ss, W1sv, W1vs, W1vvs, W1vvv, E);
    stage2_kernel<<<gE, 128>>>(edge_s, edge_v, eidx, W2ss, W2vvs, W2sv, W2vs, W2vvv, E);
    update_kernel<<<gN, 64>>>(node_s, node_v, W3ss, W3vvs, W3sv, W3vs, W3vvv,
                              Lms, Lmv, Lus, Luv, out, N);
}

// round 17
// speedup vs baseline: 1.6857x; 1.6857x over previous
#include <cuda_runtime.h>

// ---------------- scratch (sizes fixed: N=50000, E=400000) ----------------
__device__ float g_agg [50048  * 80];   // per-node gated sums: 32 silu'd scalars + 48 vec comps
__device__ float g_mid [400000 * 40];   // stage-1 per-edge intermediate (e-major)

#define I2f   0.70710678118654752f
#define I3f   0.57735026918962576f
#define R128f 0.08838834764831845f
#define R32f  0.17677669529663687f

__device__ __forceinline__ float sigm_f(float x) {
    return __fdividef(1.f, 1.f + __expf(-x));
}

__device__ __forceinline__ void wload(float* __restrict__ dst, const float* __restrict__ src,
                                      int nf4, float sc, int tid, int nt) {
    for (int t = tid; t < nf4; t += nt) {
        float4 v = reinterpret_cast<const float4*>(src)[t];
        v.x *= sc; v.y *= sc; v.z *= sc; v.w *= sc;
        reinterpret_cast<float4*>(dst)[t] = v;
    }
}
__device__ __forceinline__ void wslice(float* __restrict__ dst, const float* __restrict__ src,
                                       int rows, int srcF4, int dstF4, int off4,
                                       float sc, int tid) {
    int n = rows * dstF4;
    for (int t = tid; t < n; t += 128) {
        int r = t / dstF4, o = t - r * dstF4;
        float4 v = reinterpret_cast<const float4*>(src)[r * srcF4 + off4 + o];
        v.x *= sc; v.y *= sc; v.z *= sc; v.w *= sc;
        reinterpret_cast<float4*>(dst)[t] = v;
    }
}
template<int K4>
__device__ __forceinline__ void fma_k(float* acc, const float* __restrict__ w, float p) {
#pragma unroll
    for (int k = 0; k < K4; k++) {
        float4 ww = reinterpret_cast<const float4*>(w)[k];
        acc[4 * k + 0] += p * ww.x; acc[4 * k + 1] += p * ww.y;
        acc[4 * k + 2] += p * ww.z; acc[4 * k + 3] += p * ww.w;
    }
}
__device__ __forceinline__ void fma_vo8(float* vo, const float* A, float bx, float by, float bz) {
#pragma unroll
    for (int k = 0; k < 8; k++) {
        vo[3 * k + 0] += A[k] * bx; vo[3 * k + 1] += A[k] * by; vo[3 * k + 2] += A[k] * bz;
    }
}
__device__ __forceinline__ void fma_cross8(float* vo, const float* __restrict__ w,
                                           float cx, float cy, float cz) {
#pragma unroll
    for (int q = 0; q < 2; q++) {
        float4 ww = reinterpret_cast<const float4*>(w)[q];
        vo[12 * q + 0]  += cx * ww.x; vo[12 * q + 1]  += cy * ww.x; vo[12 * q + 2]  += cz * ww.x;
        vo[12 * q + 3]  += cx * ww.y; vo[12 * q + 4]  += cy * ww.y; vo[12 * q + 5]  += cz * ww.y;
        vo[12 * q + 6]  += cx * ww.z; vo[12 * q + 7]  += cy * ww.z; vo[12 * q + 8]  += cz * ww.z;
        vo[12 * q + 9]  += cx * ww.w; vo[12 * q + 10] += cy * ww.w; vo[12 * q + 11] += cz * ww.w;
    }
}
__device__ __forceinline__ void ld_f(float* dst, const float* __restrict__ src, int nf4) {
#pragma unroll
    for (int q = 0; q < 6; q++)
        if (q < nf4) reinterpret_cast<float4*>(dst)[q] =
            __ldg(reinterpret_cast<const float4*>(src) + q);
}

// ---------------- kernels ----------------
__global__ void zero_kernel(int n) {
    int i = blockIdx.x * 256 + threadIdx.x;
    if (i < n) g_agg[i] = 0.f;
}

// stage1 fused: all 5 paths per edge, inputs gathered once -> g_mid[e][0:40)
__global__ __launch_bounds__(128, 5) void stage1_kernel(
    const float* __restrict__ ns, const float* __restrict__ nv,
    const int* __restrict__ eidx,
    const float* __restrict__ W1ss, const float* __restrict__ W1sv,
    const float* __restrict__ W1vs, const float* __restrict__ W1vvs,
    const float* __restrict__ W1vvv, int E)
{
    __shared__ float wss[4096], wvvs[1024], wsv[1024], wvs[1024], wvvv[512];
    int tid = threadIdx.x;
    wload(wss,  W1ss,  1024, I2f / 16.f,     tid, 128);
    wload(wvvs, W1vvs,  256, I2f * I3f / 8.f, tid, 128);
    wload(wsv,  W1sv,   256, I3f * R128f,    tid, 128);
    wload(wvs,  W1vs,   256, I3f * R128f,    tid, 128);
    wload(wvvv, W1vvv,  128, I2f * I3f / 8.f, tid, 128);
    __syncthreads();
    int e = blockIdx.x * 128 + tid;
    if (e >= E) return;
    int r = eidx[e], c = eidx[E + e];

    float s1[16], s2[16], v1[24], v2[24];
    ld_f(s1, ns + (size_t)r * 16, 4);
    ld_f(s2, ns + (size_t)c * 16, 4);
    ld_f(v1, nv + (size_t)r * 24, 6);
    ld_f(v2, nv + (size_t)c * 24, 6);

    // ---- scalar paths ----
    {
        float acc[16];
#pragma unroll
        for (int k = 0; k < 16; k++) acc[k] = 0.f;
#pragma unroll 1
        for (int i = 0; i < 16; i++) {
            float a = s1[i];
#pragma unroll 2
            for (int j = 0; j < 16; j++)
                fma_k<4>(acc, &wss[(i * 16 + j) * 16], a * s2[j]);
        }
#pragma unroll 1
        for (int i = 0; i < 8; i++) {
            float ax = v1[3 * i], ay = v1[3 * i + 1], az = v1[3 * i + 2];
#pragma unroll 2
            for (int j = 0; j < 8; j++) {
                float d = ax * v2[3 * j] + ay * v2[3 * j + 1] + az * v2[3 * j + 2];
                fma_k<4>(acc, &wvvs[(i * 8 + j) * 16], d);
            }
        }
        float* o = &g_mid[(size_t)e * 40];
#pragma unroll
        for (int q = 0; q < 4; q++)
            reinterpret_cast<float4*>(o)[q] = reinterpret_cast<float4*>(acc)[q];
    }
    // ---- vector paths ----
    {
        float vo[24];
#pragma unroll
        for (int k = 0; k < 24; k++) vo[k] = 0.f;
#pragma unroll 1
        for (int j = 0; j < 8; j++) {
            float A[8];
#pragma unroll
            for (int k = 0; k < 8; k++) A[k] = 0.f;
#pragma unroll 2
            for (int i = 0; i < 16; i++)
                fma_k<2>(A, &wsv[(i * 8 + j) * 8], s1[i]);
            fma_vo8(vo, A, v2[3 * j], v2[3 * j + 1], v2[3 * j + 2]);
        }
#pragma unroll 1
        for (int i = 0; i < 8; i++) {
            float A[8];
#pragma unroll
            for (int k = 0; k < 8; k++) A[k] = 0.f;
#pragma unroll 2
            for (int j = 0; j < 16; j++)
                fma_k<2>(A, &wvs[(i * 16 + j) * 8], s2[j]);
            fma_vo8(vo, A, v1[3 * i], v1[3 * i + 1], v1[3 * i + 2]);
        }
#pragma unroll 1
        for (int i = 0; i < 8; i++) {
            float ax = v1[3 * i], ay = v1[3 * i + 1], az = v1[3 * i + 2];
#pragma unroll 1
            for (int j = 0; j < 8; j++) {
                float bx = v2[3 * j], by = v2[3 * j + 1], bz = v2[3 * j + 2];
                fma_cross8(vo, &wvvv[(i * 8 + j) * 8],
                           ay * bz - az * by, az * bx - ax * bz, ax * by - ay * bx);
            }
        }
        float* o = &g_mid[(size_t)e * 40 + 16];
#pragma unroll
        for (int q = 0; q < 6; q++)
            reinterpret_cast<float4*>(o)[q] = reinterpret_cast<float4*>(vo)[q];
    }
}

// stage2 fused: 3 scalar k-chunks (silu->atomic; gates->regs) then 2 vector k-chunks
// using register gates.
__global__ __launch_bounds__(128, 5) void stage2_kernel(
    const float* __restrict__ edge_s, const float* __restrict__ edge_v,
    const int* __restrict__ eidx,
    const float* __restrict__ W2ss, const float* __restrict__ W2vvs,
    const float* __restrict__ W2sv, const float* __restrict__ W2vs,
    const float* __restrict__ W2vvv, int E)
{
    __shared__ float ws[2048], wd[1024];          // scalar chunk slices
    __shared__ float wsv[1024], wvs[512], wvvv[512]; // vector chunk slices
    int tid = threadIdx.x;
    int e = blockIdx.x * 128 + tid;
    bool act = e < E;
    int c = 0;
    float ms[16], mv[24], es[8], ev[24];
    if (act) {
        c = eidx[E + e];
        const float* m = &g_mid[(size_t)e * 40];
#pragma unroll
        for (int q = 0; q < 4; q++) reinterpret_cast<float4*>(ms)[q] = reinterpret_cast<const float4*>(m)[q];
#pragma unroll
        for (int q = 0; q < 6; q++) reinterpret_cast<float4*>(mv)[q] = reinterpret_cast<const float4*>(m)[4 + q];
        ld_f(es, edge_s + (size_t)e * 8, 2);
        ld_f(ev, edge_v + (size_t)e * 24, 6);
    }
    float gate[16];

    // ---- scalar chunks ----
#pragma unroll 1
    for (int ch = 0; ch < 3; ch++) {
        __syncthreads();
        wslice(ws, W2ss, 128, 12, 4, ch * 4, I2f * R128f, tid);
        wslice(wd, W2vvs, 64, 12, 4, ch * 4, I2f * I3f / 8.f, tid);
        __syncthreads();
        if (!act) continue;
        float acc[16];
#pragma unroll
        for (int k = 0; k < 16; k++) acc[k] = 0.f;
#pragma unroll 1
        for (int i = 0; i < 16; i++) {
            float a = ms[i];
#pragma unroll 2
            for (int j = 0; j < 8; j++)
                fma_k<4>(acc, &ws[(i * 8 + j) * 16], a * es[j]);
        }
#pragma unroll 1
        for (int i = 0; i < 8; i++) {
            float ax = mv[3 * i], ay = mv[3 * i + 1], az = mv[3 * i + 2];
#pragma unroll 2
            for (int j = 0; j < 8; j++) {
                float d = ax * ev[3 * j] + ay * ev[3 * j + 1] + az * ev[3 * j + 2];
                fma_k<4>(acc, &wd[(i * 8 + j) * 16], d);
            }
        }
        if (ch < 2) {
            float* dst = &g_agg[(size_t)c * 80 + ch * 16];
#pragma unroll
            for (int t = 0; t < 16; t++)
                atomicAdd(dst + t, acc[t] * sigm_f(acc[t]));   // silu
        } else {
#pragma unroll
            for (int t = 0; t < 16; t++)
                gate[t] = sigm_f(acc[t]);
        }
    }

    // ---- vector chunks (gates in registers) ----
#pragma unroll 1
    for (int ch = 0; ch < 2; ch++) {
        __syncthreads();
        wslice(wsv, W2sv, 128, 4, 2, ch * 2, I3f * R128f, tid);
        wslice(wvs, W2vs, 64, 4, 2, ch * 2, I3f / 8.f, tid);
        wslice(wvvv, W2vvv, 64, 4, 2, ch * 2, I2f * I3f / 8.f, tid);
        __syncthreads();
        if (!act) continue;
        float vo[24];
#pragma unroll
        for (int k = 0; k < 24; k++) vo[k] = 0.f;
#pragma unroll 1
        for (int j = 0; j < 8; j++) {
            float A[8];
#pragma unroll
            for (int k = 0; k < 8; k++) A[k] = 0.f;
#pragma unroll 2
            for (int i = 0; i < 16; i++)
                fma_k<2>(A, &wsv[(i * 8 + j) * 8], ms[i]);
            fma_vo8(vo, A, ev[3 * j], ev[3 * j + 1], ev[3 * j + 2]);
        }
#pragma unroll 1
        for (int i = 0; i < 8; i++) {
            float A[8];
#pragma unroll
            for (int k = 0; k < 8; k++) A[k] = 0.f;
#pragma unroll 2
            for (int j = 0; j < 8; j++)
                fma_k<2>(A, &wvs[(i * 8 + j) * 8], es[j]);
            fma_vo8(vo, A, mv[3 * i], mv[3 * i + 1], mv[3 * i + 2]);
        }
#pragma unroll 1
        for (int i = 0; i < 8; i++) {
            float ax = mv[3 * i], ay = mv[3 * i + 1], az = mv[3 * i + 2];
#pragma unroll 1
            for (int j = 0; j < 8; j++) {
                float bx = ev[3 * j], by = ev[3 * j + 1], bz = ev[3 * j + 2];
                fma_cross8(vo, &wvvv[(i * 8 + j) * 8],
                           ay * bz - az * by, az * bx - ax * bz, ax * by - ay * bx);
            }
        }
#pragma unroll
        for (int t = 0; t < 8; t++) {
            float g = gate[ch * 8 + t];
            float* dst = &g_agg[(size_t)c * 80 + 32 + (ch * 8 + t) * 3];
            atomicAdd(dst + 0, vo[3 * t + 0] * g);
            atomicAdd(dst + 1, vo[3 * t + 1] * g);
            atomicAdd(dst + 2, vo[3 * t + 2] * g);
        }
    }
}

// update fused (folds Lms/Lmv + Lus/Luv): reads g_agg[n,80] directly, writes out.
__global__ __launch_bounds__(128, 4) void update_kernel(
    const float* __restrict__ ns, const float* __restrict__ nv,
    const float* __restrict__ W3ss, const float* __restrict__ W3vvs,
    const float* __restrict__ W3sv, const float* __restrict__ W3vs,
    const float* __restrict__ W3vvv,
    const float* __restrict__ Lms, const float* __restrict__ Lmv,
    const float* __restrict__ Lus, const float* __restrict__ Luv,
    float* __restrict__ out, int N)
{
    __shared__ float ws[4096], wd[1024];              // scalar slices
    __shared__ float wsv[1024], wvs[1024], wvvv[512]; // vector slices
    __shared__ float lms[512], lmv[128], lus[512], luv[128];
    int tid = threadIdx.x;
    wload(lms, Lms, 128, R32f, tid, 128);
    wload(lmv, Lmv, 32, 0.25f, tid, 128);
    wload(lus, Lus, 128, R32f, tid, 128);
    wload(luv, Luv, 32, 0.25f, tid, 128);
    __syncthreads();
    int n = blockIdx.x * 128 + tid;
    bool act = n < N;

    float s1[16], v1[24], s2[16], v2[24];
    if (act) {
        ld_f(s1, ns + (size_t)n * 16, 4);
        ld_f(v1, nv + (size_t)n * 24, 6);
        // ---- fold Lms/Lmv from aggregated (post-gate) sums ----
        const float* a = &g_agg[(size_t)n * 80];
#pragma unroll
        for (int k = 0; k < 16; k++) s2[k] = 0.f;
#pragma unroll 1
        for (int i = 0; i < 32; i++)
            fma_k<4>(s2, &lms[i * 16], a[i]);
#pragma unroll
        for (int k = 0; k < 24; k++) v2[k] = 0.f;
#pragma unroll 1
        for (int i = 0; i < 16; i++) {
            float ax = a[32 + 3 * i], ay = a[32 + 3 * i + 1], az = a[32 + 3 * i + 2];
            const float* w = &lmv[i * 8];
#pragma unroll
            for (int k = 0; k < 8; k++) {
                float ww = w[k];
                v2[3 * k + 0] += ax * ww; v2[3 * k + 1] += ay * ww; v2[3 * k + 2] += az * ww;
            }
        }
    }
    float os[16], ov[24], gate[16];
#pragma unroll
    for (int k = 0; k < 16; k++) os[k] = 0.f;
#pragma unroll
    for (int k = 0; k < 24; k++) ov[k] = 0.f;

    // ---- scalar chunks ----
#pragma unroll 1
    for (int ch = 0; ch < 3; ch++) {
        __syncthreads();
        wslice(ws, W3ss, 256, 12, 4, ch * 4, I2f / 16.f, tid);
        wslice(wd, W3vvs, 64, 12, 4, ch * 4, I2f * I3f / 8.f, tid);
        __syncthreads();
        if (!act) continue;
        float acc[16];
#pragma unroll
        for (int k = 0; k < 16; k++) acc[k] = 0.f;
#pragma unroll 1
        for (int i = 0; i < 16; i++) {
            float a = s1[i];
#pragma unroll 2
            for (int j = 0; j < 16; j++)
                fma_k<4>(acc, &ws[(i * 16 + j) * 16], a * s2[j]);
        }
#pragma unroll 1
        for (int i = 0; i < 8; i++) {
            float ax = v1[3 * i], ay = v1[3 * i + 1], az = v1[3 * i + 2];
#pragma unroll 2
            for (int j = 0; j < 8; j++) {
                float d = ax * v2[3 * j] + ay * v2[3 * j + 1] + az * v2[3 * j + 2];
                fma_k<4>(acc, &wd[(i * 8 + j) * 16], d);
            }
        }
        if (ch < 2) {
#pragma unroll 1
            for (int t = 0; t < 16; t++) {
                float a = acc[t] * sigm_f(acc[t]);           // silu
                fma_k<4>(os, &lus[(ch * 16 + t) * 16], a);   // fold Lus
            }
        } else {
#pragma unroll
            for (int t = 0; t < 16; t++)
                gate[t] = sigm_f(acc[t]);
        }
    }

    // ---- vector chunks ----
#pragma unroll 1
    for (int ch = 0; ch < 2; ch++) {
        __syncthreads();
        wslice(wsv, W3sv, 128, 4, 2, ch * 2, I3f * R128f, tid);
        wslice(wvs, W3vs, 128, 4, 2, ch * 2, I3f * R128f, tid);
        wslice(wvvv, W3vvv, 64, 4, 2, ch * 2, I2f * I3f / 8.f, tid);
        __syncthreads();
        if (!act) continue;
        float vo[24];
#pragma unroll
        for (int k = 0; k < 24; k++) vo[k] = 0.f;
#pragma unroll 1
        for (int j = 0; j < 8; j++) {
            float A[8];
#pragma unroll
            for (int k = 0; k < 8; k++) A[k] = 0.f;
#pragma unroll 2
            for (int i = 0; i < 16; i++)
                fma_k<2>(A, &wsv[(i * 8 + j) * 8], s1[i]);
            fma_vo8(vo, A, v2[3 * j], v2[3 * j + 1], v2[3 * j + 2]);
        }
#pragma unroll 1
        for (int i = 0; i < 8; i++) {
            float A[8];
#pragma unroll
            for (int k = 0; k < 8; k++) A[k] = 0.f;
#pragma unroll 2
            for (int j = 0; j < 16; j++)
                fma_k<2>(A, &wvs[(i * 16 + j) * 8], s2[j]);
            fma_vo8(vo, A, v1[3 * i], v1[3 * i + 1], v1[3 * i + 2]);
        }
#pragma unroll 1
        for (int i = 0; i < 8; i++) {
            float ax = v1[3 * i], ay = v1[3 * i + 1], az = v1[3 * i + 2];
#pragma unroll 1
            for (int j = 0; j < 8; j++) {
                float bx = v2[3 * j], by = v2[3 * j + 1], bz = v2[3 * j + 2];
                float cx = ay * bz - az * by, cy = az * bx - ax * bz, cz = ax * by - ay * bx;
                fma_cross8(vo, &wvvv[(i * 8 + j) * 8], cx, cy, cz);
            }
        }
        // gate + fold Luv
#pragma unroll 1
        for (int t = 0; t < 8; t++) {
            float g = gate[ch * 8 + t];
            float gx = vo[3 * t + 0] * g, gy = vo[3 * t + 1] * g, gz = vo[3 * t + 2] * g;
            const float* w = &luv[(ch * 8 + t) * 8];
#pragma unroll
            for (int k = 0; k < 8; k++) {
                float ww = w[k];
                ov[3 * k + 0] += gx * ww; ov[3 * k + 1] += gy * ww; ov[3 * k + 2] += gz * ww;
            }
        }
    }
    if (act) {
        float* o = out + (size_t)n * 40;
#pragma unroll
        for (int q = 0; q < 4; q++) reinterpret_cast<float4*>(o)[q] = reinterpret_cast<float4*>(os)[q];
#pragma unroll
        for (int q = 0; q < 6; q++) reinterpret_cast<float4*>(o)[4 + q] = reinterpret_cast<float4*>(ov)[q];
    }
}

// ---------------- launch ----------------
extern "C" void kernel_launch(void* const* d_in, const int* in_sizes, int n_in,
                              void* d_out, int out_size) {
    const float* node_s = (const float*)d_in[0];
    const float* node_v = (const float*)d_in[1];
    const float* edge_s = (const float*)d_in[3];
    const float* edge_v = (const float*)d_in[4];
    const int*   eidx   = (const int*)d_in[5];
    const float* W1ss = (const float*)d_in[6];
    const float* W1sv = (const float*)d_in[7];
    const float* W1vs = (const float*)d_in[8];
    const float* W1vvs = (const float*)d_in[9];
    const float* W1vvv = (const float*)d_in[10];
    const float* W2ss = (const float*)d_in[11];
    const float* W2sv = (const float*)d_in[12];
    const float* W2vs = (const float*)d_in[13];
    const float* W2vvs = (const float*)d_in[14];
    const float* W2vvv = (const float*)d_in[15];
    const float* Lms = (const float*)d_in[16];
    const float* Lmv = (const float*)d_in[17];
    const float* W3ss = (const float*)d_in[18];
    const float* W3sv = (const float*)d_in[19];
    const float* W3vs = (const float*)d_in[20];
    const float* W3vvs = (const float*)d_in[21];
    const float* W3vvv = (const float*)d_in[22];
    const float* Lus = (const float*)d_in[23];
    const float* Luv = (const float*)d_in[24];
    float* out = (float*)d_out;

    int N = in_sizes[0] / 16;
    int E = in_sizes[3] / 8;
    int gE = (E + 127) / 128;
    int gN = (N + 127) / 128;

    zero_kernel<<<(N * 80 + 255) / 256, 256>>>(N * 80);
    stage1_kernel<<<gE, 128>>>(node_s, node_v, eidx, W1ss, W1sv, W1vs, W1vvs, W1vvv, E);
    stage2_kernel<<<gE, 128>>>(edge_s, edge_v, eidx, W2ss, W2vvs, W2sv, W2vs, W2vvv, E);
    update_kernel<<<gN, 128>>>(node_s, node_v, W3ss, W3vvs, W3sv, W3vs, W3vvv,
                               Lms, Lmv, Lus, Luv, out, N);
}